// round 1
// baseline (speedup 1.0000x reference)
#include <cuda_runtime.h>

// LIIF render, fully fused fp32 baseline.
// Shapes are fixed by the problem: N=4, C=64, Hf=Wf=64, h=w=256.
// Each block: 32 queries x 1 batch image, loops 4 corner samples,
// runs the 68->256->256->256->256->3 MLP with weights staged through
// double-buffered shared-memory K-tiles, accumulates area-weighted preds.

namespace {

constexpr int TM        = 32;    // queries per block
constexpr int KT        = 16;    // K-tile for weight staging
constexpr int D         = 256;   // hidden dim
constexpr int XS_STRIDE = 257;   // activation row stride (conflict-free writes)
constexpr int NTHR      = 256;

// Y[32,256] = act(X[32,Kin] @ W[Kin,256] + B), written back into XsF.
// Thread layout: warp = row group (4 rows), lane = base column; each thread
// computes 4 rows x 8 cols (cols = j*32+lane -> stride-1 LDS, conflict-free).
__device__ __forceinline__ void run_layer(
    float* XsF, float* WsF,
    const float* __restrict__ W, const float* __restrict__ B,
    int Kin, bool do_relu, int tid)
{
    const int warp = tid >> 5;
    const int lane = tid & 31;
    const int row0 = warp * 4;

    float acc[4][8];
#pragma unroll
    for (int i = 0; i < 4; i++)
#pragma unroll
        for (int j = 0; j < 8; j++) acc[i][j] = 0.f;

    const int ntiles = (Kin + KT - 1) / KT;
    const float4* Wg4 = reinterpret_cast<const float4*>(W);
    float4* Ws4 = reinterpret_cast<float4*>(WsF);

    // Preload tile 0 (zero-fill rows >= Kin so partial tiles contribute 0).
#pragma unroll
    for (int r = 0; r < 4; r++) {
        const int f = tid + NTHR * r;        // float4 index within tile
        const int k = f >> 6;                // 64 float4 per row of 256
        Ws4[f] = (k < Kin) ? Wg4[f] : make_float4(0.f, 0.f, 0.f, 0.f);
    }
    __syncthreads();

    int buf = 0;
    for (int tile = 0; tile < ntiles; tile++) {
        // Prefetch next tile into registers (latency overlapped with compute).
        float4 nxt[4];
        const bool has_next = (tile + 1 < ntiles);
        if (has_next) {
            const int k0n = (tile + 1) * KT;
#pragma unroll
            for (int r = 0; r < 4; r++) {
                const int f = tid + NTHR * r;
                const int k = k0n + (f >> 6);
                nxt[r] = (k < Kin) ? Wg4[k0n * 64 + f]
                                   : make_float4(0.f, 0.f, 0.f, 0.f);
            }
        }

        const float* Wcur = WsF + buf * (KT * D);
        const int kbase = tile * KT;
#pragma unroll
        for (int kk = 0; kk < KT; kk++) {
            float xf[4];
#pragma unroll
            for (int i = 0; i < 4; i++)
                xf[i] = XsF[(row0 + i) * XS_STRIDE + kbase + kk];  // broadcast LDS
#pragma unroll
            for (int j = 0; j < 8; j++) {
                const float wv = Wcur[kk * D + j * 32 + lane];     // stride-1 LDS
#pragma unroll
                for (int i = 0; i < 4; i++)
                    acc[i][j] = fmaf(xf[i], wv, acc[i][j]);
            }
        }

        if (has_next) {
            __syncthreads();   // all warps done computing current tile
            float4* Wnx4 = reinterpret_cast<float4*>(WsF + ((buf ^ 1) * (KT * D)));
#pragma unroll
            for (int r = 0; r < 4; r++) Wnx4[tid + NTHR * r] = nxt[r];
            __syncthreads();   // stores visible before next tile's compute
            buf ^= 1;
        }
    }

    __syncthreads();           // all reads of XsF finished before overwrite
#pragma unroll
    for (int j = 0; j < 8; j++) {
        const int col = j * 32 + lane;
        const float bv = B[col];
#pragma unroll
        for (int i = 0; i < 4; i++) {
            float v = acc[i][j] + bv;
            if (do_relu) v = fmaxf(v, 0.f);
            XsF[(row0 + i) * XS_STRIDE + col] = v;
        }
    }
    __syncthreads();
}

__global__ __launch_bounds__(NTHR, 3)
void liif_kernel(const float* __restrict__ feat,
                 const float* __restrict__ w0, const float* __restrict__ b0,
                 const float* __restrict__ w1, const float* __restrict__ b1,
                 const float* __restrict__ w2, const float* __restrict__ b2,
                 const float* __restrict__ w3, const float* __restrict__ b3,
                 const float* __restrict__ w4, const float* __restrict__ b4,
                 float* __restrict__ out)
{
    extern __shared__ float smem[];
    float* XsF = smem;                       // 32 * 257 floats (activations)
    float* WsF = smem + TM * XS_STRIDE;      // 2 * 16 * 256 floats (W tiles)

    __shared__ int   s_idx[4][TM];
    __shared__ float s_rel[4][2][TM];
    __shared__ float s_wt[4][TM];
    __shared__ float s_acc[TM][4];

    const int tid = threadIdx.x;
    const int n  = blockIdx.y;
    const int q0 = blockIdx.x * TM;

    // ---- per-query geometry for all 4 corners (matches JAX fp32 semantics) ----
    if (tid < TM) {
        const int q = q0 + tid;
        const int yq = q >> 8;
        const int xq = q & 255;
        const float c0 = (2.f * (float)yq + 1.f) * (1.f / 256.f) - 1.f;
        const float c1 = (2.f * (float)xq + 1.f) * (1.f / 256.f) - 1.f;
        const float lo = (float)(-1.0 + 1e-6);
        const float hi = (float)( 1.0 - 1e-6);
        float areas[4];
#pragma unroll
        for (int t = 0; t < 4; t++) {
            // corner order: t=0:(-1,-1) t=1:(-1,+1) t=2:(+1,-1) t=3:(+1,+1)
            const double vx = (t < 2) ? -1.0 : 1.0;
            const double vy = (t & 1) ? 1.0 : -1.0;
            const float shx = (float)(vx * (1.0 / 64.0) + 1e-6);
            const float shy = (float)(vy * (1.0 / 64.0) + 1e-6);
            const float cc0 = fminf(fmaxf(c0 + shx, lo), hi);
            const float cc1 = fminf(fmaxf(c1 + shy, lo), hi);
            int iy = (int)rintf(((cc0 + 1.f) * 64.f - 1.f) * 0.5f);  // round-half-even
            int ix = (int)rintf(((cc1 + 1.f) * 64.f - 1.f) * 0.5f);
            iy = min(max(iy, 0), 63);
            ix = min(max(ix, 0), 63);
            const float qc0 = (2.f * (float)iy + 1.f) * (1.f / 64.f) - 1.f;
            const float qc1 = (2.f * (float)ix + 1.f) * (1.f / 64.f) - 1.f;
            const float r0 = (c0 - qc0) * 64.f;
            const float r1 = (c1 - qc1) * 64.f;
            s_idx[t][tid]    = iy * 64 + ix;
            s_rel[t][0][tid] = r0;
            s_rel[t][1][tid] = r1;
            areas[t] = fabsf(r0 * r1) + 1e-9f;
        }
        const float tot = areas[0] + areas[1] + areas[2] + areas[3];
#pragma unroll
        for (int t = 0; t < 4; t++) s_wt[t][tid] = areas[3 - t] / tot;  // reversed pairing
        s_acc[tid][0] = 0.f; s_acc[tid][1] = 0.f; s_acc[tid][2] = 0.f;
    }
    __syncthreads();

    // ---- 4 corner samples, each a full MLP pass ----
    for (int t = 0; t < 4; t++) {
        // Build X[32][68]: gather q_feat (feat is NCHW; feat_flat[n,idx,c] = feat[n,c,idx])
        {
            const int i    = tid & 31;   // query row (lanes vary idx -> coalesced LDG)
            const int chb  = tid >> 5;   // channel base 0..7
            const int idx  = s_idx[t][i];
            const float* fb = feat + (size_t)n * (64 * 4096) + idx;
#pragma unroll
            for (int j = 0; j < 8; j++) {
                const int ch = chb + j * 8;
                XsF[i * XS_STRIDE + ch] = fb[ch * 4096];
            }
            if (chb == 0) {
                XsF[i * XS_STRIDE + 64] = s_rel[t][0][i];
                XsF[i * XS_STRIDE + 65] = s_rel[t][1][i];
                XsF[i * XS_STRIDE + 66] = 0.5f;   // rel_cell = cell*scale = 0.5 exactly
                XsF[i * XS_STRIDE + 67] = 0.5f;
            } else if (chb == 1) {
#pragma unroll
                for (int c = 68; c < 80; c++)     // zero-pad for the partial K-tile
                    XsF[i * XS_STRIDE + c] = 0.f;
            }
        }
        __syncthreads();

        run_layer(XsF, WsF, w0, b0,  68, true, tid);
        run_layer(XsF, WsF, w1, b1, 256, true, tid);
        run_layer(XsF, WsF, w2, b2, 256, true, tid);
        run_layer(XsF, WsF, w3, b3, 256, true, tid);

        // Final 256->3 layer + weighted accumulation (threads 0..95: (row, outch))
        if (tid < 96) {
            const int i = tid / 3;
            const int o = tid - 3 * (tid / 3);
            float acc = b4[o];
            const float* xr = XsF + i * XS_STRIDE;
#pragma unroll 8
            for (int k = 0; k < 256; k++)
                acc = fmaf(xr[k], w4[k * 3 + o], acc);
            s_acc[i][o] += s_wt[t][i] * acc;
        }
        __syncthreads();
    }

    // ---- write NCHW output: out[n][o][q] ----
    if (tid < 96) {
        const int i = tid / 3;
        const int o = tid - 3 * (tid / 3);
        out[((size_t)n * 3 + o) * 65536 + q0 + i] = s_acc[i][o];
    }
}

} // anonymous namespace

extern "C" void kernel_launch(void* const* d_in, const int* in_sizes, int n_in,
                              void* d_out, int out_size)
{
    (void)in_sizes; (void)n_in; (void)out_size;
    const float* feat = (const float*)d_in[0];
    const float* w0 = (const float*)d_in[1];
    const float* b0 = (const float*)d_in[2];
    const float* w1 = (const float*)d_in[3];
    const float* b1 = (const float*)d_in[4];
    const float* w2 = (const float*)d_in[5];
    const float* b2 = (const float*)d_in[6];
    const float* w3 = (const float*)d_in[7];
    const float* b3 = (const float*)d_in[8];
    const float* w4 = (const float*)d_in[9];
    const float* b4 = (const float*)d_in[10];

    const size_t shmem = (size_t)(TM * XS_STRIDE + 2 * KT * D) * sizeof(float); // ~64 KB
    cudaFuncSetAttribute(liif_kernel,
                         cudaFuncAttributeMaxDynamicSharedMemorySize, (int)shmem);

    dim3 grid(65536 / TM, 4);
    liif_kernel<<<grid, NTHR, shmem>>>(feat, w0, b0, w1, b1, w2, b2, w3, b3, w4, b4,
                                       (float*)d_out);
}

// round 3
// speedup vs baseline: 5.4942x; 5.4942x over previous
#include <cuda_runtime.h>
#include <cstdint>

// LIIF render via warp-level tf32 HMMA (mma.sync m16n8k8) on sm_103.
// M=128 rows per CTA = 32 queries x 4 corner samples (corners share weights).
// X[128,256] in smem (stride 260, conflict-free A-frag reads); weights
// tf32-pre-rounded into gmem scratch and streamed via cp.async double buffer
// (stride 264, conflict-free B-frag reads). 8 warps, 64x64 warp tiles.

namespace {

constexpr int NTHR      = 256;
constexpr int QT        = 32;
constexpr int XS_STRIDE = 260;               // %32==4 -> A reads on banks 4g+tig
constexpr int WS_STRIDE = 264;               // %32==8 -> B reads on banks 8tig+g
constexpr int WS_BUF    = 32 * WS_STRIDE;    // floats per weight K-tile buffer
constexpr int NSTAGES   = 27;                // L0: 3 tiles (72k), L1..L3: 8 tiles

__device__ float g_wr[215040];               // tf32-rounded weights, [k][256] rows
__device__ __forceinline__ int layer_woff(int l) {
    return l == 0 ? 0 : l == 1 ? 18432 : l == 2 ? 83968 : 149504;
}

__device__ __forceinline__ uint32_t smem_u32(const void* p) {
    uint32_t a;
    asm("{ .reg .u64 t; cvta.to.shared.u64 t, %1; cvt.u32.u64 %0, t; }"
        : "=r"(a) : "l"(p));
    return a;
}
__device__ __forceinline__ float tf32r(float x) {
    float y; asm("cvt.rna.tf32.f32 %0, %1;" : "=f"(y) : "f"(x)); return y;
}
__device__ __forceinline__ void cp16(uint32_t dst, const void* src) {
    asm volatile("cp.async.cg.shared.global [%0], [%1], 16;"
                 :: "r"(dst), "l"(src) : "memory");
}
__device__ __forceinline__ void cp_commit() {
    asm volatile("cp.async.commit_group;" ::: "memory");
}
template <int N>
__device__ __forceinline__ void cp_wait() {
    asm volatile("cp.async.wait_group %0;" :: "n"(N) : "memory");
}

__device__ __forceinline__ void mma_tf32(float c[4], uint32_t a0, uint32_t a1,
                                         uint32_t a2, uint32_t a3,
                                         uint32_t b0, uint32_t b1) {
    asm volatile(
        "mma.sync.aligned.m16n8k8.row.col.f32.tf32.tf32.f32 "
        "{%0,%1,%2,%3}, {%4,%5,%6,%7}, {%8,%9}, {%0,%1,%2,%3};"
        : "+f"(c[0]), "+f"(c[1]), "+f"(c[2]), "+f"(c[3])
        : "r"(a0), "r"(a1), "r"(a2), "r"(a3), "r"(b0), "r"(b1));
}

// ---------- prep: tf32-round weights into [k][256] scratch (L0 padded to 72 rows) ----------
__global__ void prep_kernel(const float* __restrict__ w0, const float* __restrict__ w1,
                            const float* __restrict__ w2, const float* __restrict__ w3) {
    const int idx = blockIdx.x * blockDim.x + threadIdx.x;
    if (idx >= 215040) return;
    int l, k;
    if (idx < 18432) { l = 0; k = idx >> 8; }
    else { const int rem = idx - 18432; l = 1 + rem / 65536; k = (rem & 65535) >> 8; }
    const int nn = idx & 255;
    const float* w = (l == 0) ? w0 : (l == 1) ? w1 : (l == 2) ? w2 : w3;
    float v = 0.f;
    if (l > 0 || k < 68) v = w[k * 256 + nn];
    g_wr[idx] = tf32r(v);
}

__device__ __forceinline__ void prefetch_stage(uint32_t ws_u, int buf, int st, int tid) {
    int l, tile;
    if (st < 3) { l = 0; tile = st; } else { l = 1 + (st - 3) / 8; tile = (st - 3) & 7; }
    const float* src = g_wr + layer_woff(l) + tile * 8192;   // 32 rows x 256
    const uint32_t dst = ws_u + (uint32_t)buf * (WS_BUF * 4);
#pragma unroll
    for (int j = 0; j < 8; j++) {
        const int i   = tid + NTHR * j;   // float4 index 0..2047
        const int row = i >> 6;
        const int f4  = i & 63;
        cp16(dst + (uint32_t)(row * WS_STRIDE + f4 * 4) * 4u, src + row * 256 + f4 * 4);
    }
    cp_commit();
}

// ---------- main kernel ----------
__global__ __launch_bounds__(NTHR, 1)
void liif_hmma_kernel(const float* __restrict__ feat, const float* __restrict__ w4,
                      const float* __restrict__ b0, const float* __restrict__ b1,
                      const float* __restrict__ b2, const float* __restrict__ b3,
                      const float* __restrict__ b4, float* __restrict__ out)
{
    extern __shared__ float smem[];
    float* Xs = smem;                             // 128 x 260 floats
    float* Ws = smem + 128 * XS_STRIDE;           // 2 x WS_BUF floats
    const uint32_t ws_u = smem_u32(Ws);

    __shared__ float s_bias[4][256];
    __shared__ float s_w4[768];
    __shared__ float s_b4[3];
    __shared__ int   s_idx[4][QT];
    __shared__ float s_rel[4][2][QT];
    __shared__ float s_wt[4][QT];
    __shared__ float s_pred[128][3];

    const int tid  = threadIdx.x;
    const int wid  = tid >> 5;
    const int lane = tid & 31;
    const int n    = blockIdx.y;
    const int q0   = blockIdx.x * QT;

    prefetch_stage(ws_u, 0, 0, tid);   // stage 0 copy overlaps setup

    for (int i = tid; i < 256; i += NTHR) {
        s_bias[0][i] = b0[i]; s_bias[1][i] = b1[i];
        s_bias[2][i] = b2[i]; s_bias[3][i] = b3[i];
    }
    for (int i = tid; i < 768; i += NTHR) s_w4[i] = w4[i];
    if (tid < 3) s_b4[tid] = b4[tid];

    // per-query geometry (validated in R1)
    if (tid < QT) {
        const int q = q0 + tid;
        const int yq = q >> 8, xq = q & 255;
        const float c0 = (2.f * (float)yq + 1.f) * (1.f / 256.f) - 1.f;
        const float c1 = (2.f * (float)xq + 1.f) * (1.f / 256.f) - 1.f;
        const float lo = (float)(-1.0 + 1e-6), hi = (float)(1.0 - 1e-6);
        float areas[4];
#pragma unroll
        for (int t = 0; t < 4; t++) {
            const double vx = (t < 2) ? -1.0 : 1.0;
            const double vy = (t & 1) ? 1.0 : -1.0;
            const float shx = (float)(vx * (1.0 / 64.0) + 1e-6);
            const float shy = (float)(vy * (1.0 / 64.0) + 1e-6);
            const float cc0 = fminf(fmaxf(c0 + shx, lo), hi);
            const float cc1 = fminf(fmaxf(c1 + shy, lo), hi);
            int iy = (int)rintf(((cc0 + 1.f) * 64.f - 1.f) * 0.5f);
            int ix = (int)rintf(((cc1 + 1.f) * 64.f - 1.f) * 0.5f);
            iy = min(max(iy, 0), 63); ix = min(max(ix, 0), 63);
            const float qc0 = (2.f * (float)iy + 1.f) * (1.f / 64.f) - 1.f;
            const float qc1 = (2.f * (float)ix + 1.f) * (1.f / 64.f) - 1.f;
            const float r0 = (c0 - qc0) * 64.f;
            const float r1 = (c1 - qc1) * 64.f;
            s_idx[t][tid] = iy * 64 + ix;
            s_rel[t][0][tid] = r0; s_rel[t][1][tid] = r1;
            areas[t] = fabsf(r0 * r1) + 1e-9f;
        }
        const float tot = areas[0] + areas[1] + areas[2] + areas[3];
#pragma unroll
        for (int t = 0; t < 4; t++) s_wt[t][tid] = areas[3 - t] / tot;
    }
    __syncthreads();

    // X build: row = corner*32 + query; cols 0..63 feat, 64-65 rel, 66-67 cell, 68-71 zero
    {
        const int t = wid & 3, chalf = wid >> 2, i = lane;
        const int row = t * QT + i;
        const int idx = s_idx[t][i];
        const float* fb = feat + (size_t)n * (64 * 4096) + idx;
        float* xr = Xs + row * XS_STRIDE;
#pragma unroll
        for (int j = 0; j < 32; j++) {
            const int ch = chalf * 32 + j;
            xr[ch] = tf32r(fb[ch * 4096]);
        }
        if (chalf == 0) {
            xr[64] = tf32r(s_rel[t][0][i]);
            xr[65] = tf32r(s_rel[t][1][i]);
            xr[66] = 0.5f; xr[67] = 0.5f;        // rel_cell*scale = 0.5 exactly (tf32-exact)
            xr[68] = 0.f; xr[69] = 0.f; xr[70] = 0.f; xr[71] = 0.f;
        }
    }
    __syncthreads();

    const int wm = wid & 1, wn = wid >> 1;       // warp tile: rows wm*64, cols wn*64
    const int g_ = lane >> 2, tig = lane & 3;
    const uint32_t* Arow = (const uint32_t*)(Xs + (wm * 64 + g_) * XS_STRIDE + tig);

    float acc[4][8][4];
#pragma unroll
    for (int mt = 0; mt < 4; mt++)
#pragma unroll
        for (int nt = 0; nt < 8; nt++)
#pragma unroll
            for (int r = 0; r < 4; r++) acc[mt][nt][r] = 0.f;

    int buf = 0;
#pragma unroll 1
    for (int st = 0; st < NSTAGES; st++) {
        int l, tile, ks;
        if (st < 3) { l = 0; tile = st; ks = (st == 2) ? 1 : 4; }
        else        { l = 1 + (st - 3) / 8; tile = (st - 3) & 7; ks = 4; }

        if (st + 1 < NSTAGES) { prefetch_stage(ws_u, buf ^ 1, st + 1, tid); cp_wait<1>(); }
        else                  { cp_wait<0>(); }
        __syncthreads();      // stage st weights visible to all warps

        const uint32_t* Wb = (const uint32_t*)(Ws + buf * WS_BUF)
                             + tig * WS_STRIDE + wn * 64 + g_;
        const uint32_t* Ab = Arow + tile * 32;

#pragma unroll 1
        for (int k8 = 0; k8 < ks; k8++) {
            const uint32_t* Ak = Ab + k8 * 8;
            uint32_t a[4][4];
#pragma unroll
            for (int mt = 0; mt < 4; mt++) {
                a[mt][0] = Ak[(mt * 16)     * XS_STRIDE];
                a[mt][1] = Ak[(mt * 16 + 8) * XS_STRIDE];
                a[mt][2] = Ak[(mt * 16)     * XS_STRIDE + 4];
                a[mt][3] = Ak[(mt * 16 + 8) * XS_STRIDE + 4];
            }
            const uint32_t* Bk = Wb + k8 * 8 * WS_STRIDE;
#pragma unroll
            for (int nt = 0; nt < 8; nt++) {
                const uint32_t bb0 = Bk[nt * 8];
                const uint32_t bb1 = Bk[4 * WS_STRIDE + nt * 8];
#pragma unroll
                for (int mt = 0; mt < 4; mt++)
                    mma_tf32(acc[mt][nt], a[mt][0], a[mt][1], a[mt][2], a[mt][3], bb0, bb1);
            }
        }
        __syncthreads();      // all warps done reading this buffer / Xs for this layer

        if (st == 2 || st == 10 || st == 18 || st == 26) {
            const int le = (st - 2) / 8;
            const bool last = (st == 26);
#pragma unroll
            for (int mt = 0; mt < 4; mt++) {
                const int r0 = wm * 64 + mt * 16 + g_;
#pragma unroll
                for (int nt = 0; nt < 8; nt++) {
                    const int c = wn * 64 + nt * 8 + 2 * tig;
                    const float bv0 = s_bias[le][c], bv1 = s_bias[le][c + 1];
                    float v00 = fmaxf(acc[mt][nt][0] + bv0, 0.f);
                    float v01 = fmaxf(acc[mt][nt][1] + bv1, 0.f);
                    float v10 = fmaxf(acc[mt][nt][2] + bv0, 0.f);
                    float v11 = fmaxf(acc[mt][nt][3] + bv1, 0.f);
                    if (!last) { v00 = tf32r(v00); v01 = tf32r(v01);
                                 v10 = tf32r(v10); v11 = tf32r(v11); }
                    Xs[r0 * XS_STRIDE + c]           = v00;
                    Xs[r0 * XS_STRIDE + c + 1]       = v01;
                    Xs[(r0 + 8) * XS_STRIDE + c]     = v10;
                    Xs[(r0 + 8) * XS_STRIDE + c + 1] = v11;
                    acc[mt][nt][0] = 0.f; acc[mt][nt][1] = 0.f;
                    acc[mt][nt][2] = 0.f; acc[mt][nt][3] = 0.f;
                }
            }
            __syncthreads();
        }
        buf ^= 1;
    }

    // final 256->3 layer in fp32 SIMT
    if (tid < 128) {
        const float* xr = Xs + tid * XS_STRIDE;
        float a0 = s_b4[0], a1 = s_b4[1], a2 = s_b4[2];
#pragma unroll 8
        for (int k = 0; k < 256; k++) {
            const float y = xr[k];
            const float* wr = &s_w4[k * 3];
            a0 = fmaf(y, wr[0], a0);
            a1 = fmaf(y, wr[1], a1);
            a2 = fmaf(y, wr[2], a2);
        }
        s_pred[tid][0] = a0; s_pred[tid][1] = a1; s_pred[tid][2] = a2;
    }
    __syncthreads();

    // area-weighted combine + NCHW output
    if (tid < 96) {
        const int i = tid / 3;
        const int o = tid - 3 * (tid / 3);
        float v = 0.f;
#pragma unroll
        for (int t = 0; t < 4; t++) v += s_wt[t][i] * s_pred[t * 32 + i][o];
        out[((size_t)n * 3 + o) * 65536 + q0 + i] = v;
    }
}

} // anonymous namespace

extern "C" void kernel_launch(void* const* d_in, const int* in_sizes, int n_in,
                              void* d_out, int out_size)
{
    (void)in_sizes; (void)n_in; (void)out_size;
    const float* feat = (const float*)d_in[0];
    const float* w0 = (const float*)d_in[1];
    const float* b0 = (const float*)d_in[2];
    const float* w1 = (const float*)d_in[3];
    const float* b1 = (const float*)d_in[4];
    const float* w2 = (const float*)d_in[5];
    const float* b2 = (const float*)d_in[6];
    const float* w3 = (const float*)d_in[7];
    const float* b3 = (const float*)d_in[8];
    const float* w4 = (const float*)d_in[9];
    const float* b4 = (const float*)d_in[10];

    prep_kernel<<<(215040 + 255) / 256, 256>>>(w0, w1, w2, w3);

    const size_t shmem = (size_t)(128 * XS_STRIDE + 2 * WS_BUF) * sizeof(float); // 200704 B
    cudaFuncSetAttribute(liif_hmma_kernel,
                         cudaFuncAttributeMaxDynamicSharedMemorySize, (int)shmem);
    dim3 grid(65536 / QT, 4);
    liif_hmma_kernel<<<grid, NTHR, shmem>>>(feat, w4, b0, b1, b2, b3, b4, (float*)d_out);
}